// round 1
// baseline (speedup 1.0000x reference)
#include <cuda_runtime.h>
#include <math.h>

// Problem constants
#define PD 3
#define ND 4096
#define FD 1024
#define HD 8
#define DD 8
#define EMB 64      // H*D
#define ATTD 128
#define CD 16
#define MSEG 4      // m-dimension split for occupancy
#define TM 32       // m-chunk staged in smem

// ---------------- scratch (static device memory; no allocations) -------------
__device__ __align__(16) float  g_fts [PD * ND * EMB];        // [p][n][h*8+d]
__device__ __align__(16) float2 g_ab1 [PD * ND * HD];         // (exp(f1), exp(0.01 f1))
__device__ __align__(16) float2 g_ab2 [PD * ND * HD];         // (exp(f2), exp(0.01 f2))
__device__ __align__(16) float  g_part[MSEG * PD * ND * 72];  // per-seg partial: 64 acc + 8 Z

// ---------------- K1: fts[p][n][c] = sum_f inputs[p][n][f] * W[p][c/8][f][c%8]
__global__ __launch_bounds__(256) void k1_gemm(const float* __restrict__ inp,
                                               const float* __restrict__ W) {
    const int p  = blockIdx.y;
    const int n0 = blockIdx.x * 64;
    __shared__ float As[32][68];   // [kk][row], padded
    __shared__ float Bs[32][64];   // [kk][col]
    const int tid = threadIdx.x;
    const int tx = tid & 15, ty = tid >> 4;
    float acc[4][4] = {};
    const float* Wp = W + (size_t)p * HD * FD * DD;

    for (int k0 = 0; k0 < FD; k0 += 32) {
        // stage A tile (64 rows x 32 k), transposed into smem
        #pragma unroll
        for (int it = 0; it < 2; it++) {
            int idx = it * 256 + tid;
            int r = idx >> 3, q = idx & 7;
            float4 v = *reinterpret_cast<const float4*>(
                inp + ((size_t)(p * ND + n0 + r)) * FD + k0 + q * 4);
            As[q * 4 + 0][r] = v.x; As[q * 4 + 1][r] = v.y;
            As[q * 4 + 2][r] = v.z; As[q * 4 + 3][r] = v.w;
        }
        // stage B tile (32 k x 64 cols) from W[p,h,f,d] layout
        #pragma unroll
        for (int it = 0; it < 8; it++) {
            int idx = it * 256 + tid;
            int kk = idx >> 6, c = idx & 63;
            Bs[kk][c] = Wp[(size_t)(c >> 3) * (FD * DD) + (size_t)(k0 + kk) * DD + (c & 7)];
        }
        __syncthreads();
        #pragma unroll
        for (int kk = 0; kk < 32; kk++) {
            float4 a = *reinterpret_cast<const float4*>(&As[kk][ty * 4]);
            float4 b = *reinterpret_cast<const float4*>(&Bs[kk][tx * 4]);
            float av[4] = {a.x, a.y, a.z, a.w};
            float bv[4] = {b.x, b.y, b.z, b.w};
            #pragma unroll
            for (int i = 0; i < 4; i++)
                #pragma unroll
                for (int j = 0; j < 4; j++)
                    acc[i][j] += av[i] * bv[j];
        }
        __syncthreads();
    }
    #pragma unroll
    for (int i = 0; i < 4; i++) {
        float4 v = make_float4(acc[i][0], acc[i][1], acc[i][2], acc[i][3]);
        *reinterpret_cast<float4*>(
            g_fts + ((size_t)(p * ND + n0 + ty * 4 + i)) * EMB + tx * 4) = v;
    }
}

// ---------------- K1b: f1/f2 projections -> separable exp factors ------------
__global__ __launch_bounds__(256) void k1b_factors(const float* __restrict__ a1w,
                                                   const float* __restrict__ a1b,
                                                   const float* __restrict__ a2w,
                                                   const float* __restrict__ a2b) {
    const int p = blockIdx.y;
    const int tid = threadIdx.x;
    const int n = blockIdx.x * 32 + (tid >> 3);
    const int h = tid & 7;
    const float* f = g_fts + ((size_t)(p * ND + n)) * EMB + h * 8;
    float4 fa = *reinterpret_cast<const float4*>(f);
    float4 fb = *reinterpret_cast<const float4*>(f + 4);
    const float* w1 = a1w + (size_t)(p * HD + h) * DD;
    const float* w2 = a2w + (size_t)(p * HD + h) * DD;
    float f1 = a1b[p * HD + h];
    float f2 = a2b[p * HD + h];
    f1 += fa.x * w1[0] + fa.y * w1[1] + fa.z * w1[2] + fa.w * w1[3]
        + fb.x * w1[4] + fb.y * w1[5] + fb.z * w1[6] + fb.w * w1[7];
    f2 += fa.x * w2[0] + fa.y * w2[1] + fa.z * w2[2] + fa.w * w2[3]
        + fb.x * w2[4] + fb.y * w2[5] + fb.z * w2[6] + fb.w * w2[7];
    // exp(leaky_relu(x)) = max(exp(x), exp(0.01 x)) for x = f1[n]+f2[m]
    g_ab1[((size_t)p * ND + n) * HD + h] = make_float2(__expf(f1), __expf(0.01f * f1));
    g_ab2[((size_t)p * ND + n) * HD + h] = make_float2(__expf(f2), __expf(0.01f * f2));
}

// ---------------- K2: fused attention weights + aggregation ------------------
// CTA: 128 n-rows x 1024 m-range (mseg). 256 threads: h = tid&7, grp = tid>>3,
// each thread owns 4 consecutive n rows for one head.
__global__ __launch_bounds__(256, 2) void k2_attn(const float* __restrict__ bias) {
    const int p    = blockIdx.z;
    const int mseg = blockIdx.y;
    const int n0   = blockIdx.x * 128;
    const int tid  = threadIdx.x;
    const int h = tid & 7, grp = tid >> 3;

    __shared__ float  eb_s[128][33];   // exp(bias) tile [n_local][mm], padded
    __shared__ float4 fts_s[TM][16];   // fts tile [mm][16 float4]
    __shared__ float2 f2_s[TM][8];     // (A2,B2) per [mm][h]

    float acc[4][8] = {};
    float sum[4] = {};
    float A1[4], B1[4];
    #pragma unroll
    for (int j = 0; j < 4; j++) {
        float2 ab = g_ab1[((size_t)p * ND + n0 + grp * 4 + j) * HD + h];
        A1[j] = ab.x; B1[j] = ab.y;
    }
    const float* brow = bias + ((size_t)p * ND + n0) * ND;

    const int m_begin = mseg * (ND / MSEG);
    const int m_end   = m_begin + (ND / MSEG);
    const int jm = tid & 31, wi = tid >> 5;

    for (int m0 = m_begin; m0 < m_end; m0 += TM) {
        // stage exp(bias) tile: 128 rows x 32 m
        #pragma unroll
        for (int it = 0; it < 16; it++) {
            int i = it * 8 + wi;
            eb_s[i][jm] = __expf(brow[(size_t)i * ND + m0 + jm]);
        }
        // stage fts tile (32 m x 64)
        #pragma unroll
        for (int it = 0; it < 2; it++) {
            int idx = it * 256 + tid;
            int mm = idx >> 4, q = idx & 15;
            fts_s[mm][q] = *reinterpret_cast<const float4*>(
                g_fts + ((size_t)(p * ND + m0 + mm)) * EMB + q * 4);
        }
        // stage (A2,B2) tile
        {
            int mm = tid >> 3, hh = tid & 7;
            f2_s[mm][hh] = g_ab2[((size_t)p * ND + m0 + mm) * HD + hh];
        }
        __syncthreads();

        #pragma unroll 4
        for (int mm = 0; mm < TM; mm++) {
            float4 fa = fts_s[mm][2 * h];
            float4 fb = fts_s[mm][2 * h + 1];
            float2 ab2 = f2_s[mm][h];
            #pragma unroll
            for (int j = 0; j < 4; j++) {
                float w = fmaxf(A1[j] * ab2.x, B1[j] * ab2.y) * eb_s[grp * 4 + j][mm];
                sum[j] += w;
                acc[j][0] += w * fa.x; acc[j][1] += w * fa.y;
                acc[j][2] += w * fa.z; acc[j][3] += w * fa.w;
                acc[j][4] += w * fb.x; acc[j][5] += w * fb.y;
                acc[j][6] += w * fb.z; acc[j][7] += w * fb.w;
            }
        }
        __syncthreads();
    }

    #pragma unroll
    for (int j = 0; j < 4; j++) {
        float* out = g_part + (((size_t)mseg * PD + p) * ND + n0 + grp * 4 + j) * 72;
        float4* o4 = reinterpret_cast<float4*>(out + h * 8);
        o4[0] = make_float4(acc[j][0], acc[j][1], acc[j][2], acc[j][3]);
        o4[1] = make_float4(acc[j][4], acc[j][5], acc[j][6], acc[j][7]);
        out[64 + h] = sum[j];
    }
}

// ---------------- K3: normalize + ELU + semantic attention + classifier ------
__global__ __launch_bounds__(128) void k3_final(const float* __restrict__ h_bias,
                                                const float* __restrict__ Ws,
                                                const float* __restrict__ bsv,
                                                const float* __restrict__ u,
                                                const float* __restrict__ Wc,
                                                const float* __restrict__ bc,
                                                float* __restrict__ out,
                                                int has_final, int has_alpha) {
    const int n = blockIdx.x;
    const int t = threadIdx.x;  // 128 threads
    __shared__ float multi_s[PD][EMB];
    __shared__ float red[4 * PD];
    __shared__ float al[PD];
    __shared__ float fin[EMB];

    // combine m-segment partials, normalize, add h_bias, ELU
    for (int idx = t; idx < PD * EMB; idx += 128) {
        int p = idx / EMB, d = idx % EMB, h = d >> 3;
        float a = 0.f, Z = 0.f;
        #pragma unroll
        for (int s = 0; s < MSEG; s++) {
            const float* b = g_part + (((size_t)s * PD + p) * ND + n) * 72;
            a += b[d];
            Z += b[64 + h];
        }
        float val = a / Z + h_bias[(p * HD + h) * DD + (d & 7)];
        multi_s[p][d] = val > 0.f ? val : expm1f(val);
    }
    __syncthreads();

    // semantic attention scores
    float partial[PD];
    #pragma unroll
    for (int p = 0; p < PD; p++) {
        float s = bsv[t];
        #pragma unroll
        for (int d = 0; d < EMB; d++) s += multi_s[p][d] * Ws[d * ATTD + t];
        partial[p] = tanhf(s) * u[t];
    }
    #pragma unroll
    for (int p = 0; p < PD; p++) {
        float v = partial[p];
        #pragma unroll
        for (int o = 16; o > 0; o >>= 1) v += __shfl_down_sync(0xffffffffu, v, o);
        if ((t & 31) == 0) red[(t >> 5) * PD + p] = v;
    }
    __syncthreads();
    if (t == 0) {
        float sc[PD];
        #pragma unroll
        for (int p = 0; p < PD; p++)
            sc[p] = red[p] + red[PD + p] + red[2 * PD + p] + red[3 * PD + p];
        float mx = fmaxf(sc[0], fmaxf(sc[1], sc[2]));
        float e0 = __expf(sc[0] - mx), e1 = __expf(sc[1] - mx), e2 = __expf(sc[2] - mx);
        float Zs = e0 + e1 + e2;
        al[0] = e0 / Zs; al[1] = e1 / Zs; al[2] = e2 / Zs;
    }
    __syncthreads();

    if (has_alpha && t < PD)
        out[(size_t)ND * (CD + EMB) + (size_t)n * PD + t] = al[t];

    if (t < EMB) {
        float f = al[0] * multi_s[0][t] + al[1] * multi_s[1][t] + al[2] * multi_s[2][t];
        fin[t] = f;
        if (has_final) out[(size_t)ND * CD + (size_t)n * EMB + t] = f;
    }
    __syncthreads();

    if (t < CD) {
        float s = bc[t];
        #pragma unroll
        for (int d = 0; d < EMB; d++) s += fin[d] * Wc[d * CD + t];
        out[(size_t)n * CD + t] = s;
    }
}

// ---------------- launch ------------------------------------------------------
extern "C" void kernel_launch(void* const* d_in, const int* in_sizes, int n_in,
                              void* d_out, int out_size) {
    const float* inputs   = (const float*)d_in[0];   // [P,N,F]
    const float* bias_mat = (const float*)d_in[1];   // [P,N,N]
    const float* W        = (const float*)d_in[2];   // [P,H,F,D]
    const float* a1_w     = (const float*)d_in[3];   // [P,H,D]
    const float* a1_b     = (const float*)d_in[4];   // [P,H]
    const float* a2_w     = (const float*)d_in[5];
    const float* a2_b     = (const float*)d_in[6];
    const float* h_bias   = (const float*)d_in[7];   // [P,H,D]
    const float* Ws       = (const float*)d_in[8];   // [EMB,ATT]
    const float* bs       = (const float*)d_in[9];   // [ATT]
    const float* u        = (const float*)d_in[10];  // [ATT]
    const float* Wc       = (const float*)d_in[11];  // [EMB,C]
    const float* bc       = (const float*)d_in[12];  // [C]
    float* out = (float*)d_out;

    int has_final = (out_size >= ND * (CD + EMB)) ? 1 : 0;
    int has_alpha = (out_size >= ND * (CD + EMB + PD)) ? 1 : 0;

    k1_gemm   <<<dim3(ND / 64, PD), 256>>>(inputs, W);
    k1b_factors<<<dim3(ND / 32, PD), 256>>>(a1_w, a1_b, a2_w, a2_b);
    k2_attn   <<<dim3(ND / 128, MSEG, PD), 256>>>(bias_mat);
    k3_final  <<<ND, 128>>>(h_bias, Ws, bs, u, Wc, bc, out, has_final, has_alpha);
    (void)in_sizes; (void)n_in;
}